// round 2
// baseline (speedup 1.0000x reference)
#include <cuda_runtime.h>
#include <cstdint>
#include <cfloat>

// Shapes fixed by the problem: x is (64, 128, 4096) fp32.
#define NPOS   4096
#define NROWS  8192          // 64*128
#define NTILES 33            // tiles of 124 centers (last: 126)
#define NSTRIP 32            // 8192 rows / 256 rows-per-strip
#define GTAB   2048          // gaussian table cap (R=28 for the given widths)

// Scratch in __device__ globals (no allocations allowed).
__device__ unsigned int g_part[NSTRIP * NPOS]; // per-strip packed counts
__device__ float        g_norm[NPOS];

// ---------------------------------------------------------------------------
// K1: count peaks/valleys per column position, per row-strip.
// Each warp owns a 128-float column tile (float4 per lane), iterates 32 rows,
// accumulates packed counts (peak lo16 | valley hi16) in registers, block-
// reduces via shared atomics, and stores ONE u32 per column — no global
// atomics, no pre-zeroing (each block owns a disjoint (strip, col) region).
// dd matches the reference exactly: (x[p+1]-x[p]) - (x[p]-x[p-1]).
// ---------------------------------------------------------------------------
__global__ __launch_bounds__(256) void k_counts(const float* __restrict__ x) {
    __shared__ unsigned int scol[128];

    const int lane = threadIdx.x & 31;
    const int warp = threadIdx.x >> 5;          // 0..7
    const int tile = blockIdx.x;                // 0..32
    const int s    = tile * 124;                // tile covers x columns [s, s+128)
    const int cmax = (tile == NTILES - 1) ? (NPOS - 2) : (s + 124);
    const int p0   = s + 4 * lane + 1;

    const unsigned m0 = (p0 + 0 <= cmax) ? 0xFFFFFFFFu : 0u;
    const unsigned m1 = (p0 + 1 <= cmax) ? 0xFFFFFFFFu : 0u;
    const unsigned m2 = (p0 + 2 <= cmax) ? 0xFFFFFFFFu : 0u;
    const unsigned m3 = (p0 + 3 <= cmax) ? 0xFFFFFFFFu : 0u;

    for (int i = threadIdx.x; i < 128; i += 256) scol[i] = 0u;
    __syncthreads();

    unsigned acc0 = 0, acc1 = 0, acc2 = 0, acc3 = 0;

    const int rowbase = blockIdx.y * 256 + warp * 32;
    const float* xb = x + (size_t)rowbase * NPOS + s;

    #pragma unroll 4
    for (int k = 0; k < 32; k++) {
        float4 v = __ldcs((const float4*)(xb + (size_t)k * NPOS) + lane);
        // Seam values from the next lane (garbage in lane 31; its dependent
        // centers are always masked out by m2/m3).
        float xn0 = __shfl_down_sync(0xFFFFFFFFu, v.x, 1);
        float xn1 = __shfl_down_sync(0xFFFFFFFFu, v.y, 1);

        float d0 = v.y - v.x;
        float d1 = v.z - v.y;
        float d2 = v.w - v.z;
        float d3 = xn0 - v.w;
        float d4 = xn1 - xn0;

        float dd0 = d1 - d0;   // center p0
        float dd1 = d2 - d1;   // center p0+1
        float dd2 = d3 - d2;   // center p0+2
        float dd3 = d4 - d3;   // center p0+3

        acc0 += m0 & (((unsigned)(dd0 < 0.0f)) | (((unsigned)(dd0 > 0.0f)) << 16));
        acc1 += m1 & (((unsigned)(dd1 < 0.0f)) | (((unsigned)(dd1 > 0.0f)) << 16));
        acc2 += m2 & (((unsigned)(dd2 < 0.0f)) | (((unsigned)(dd2 > 0.0f)) << 16));
        acc3 += m3 & (((unsigned)(dd3 < 0.0f)) | (((unsigned)(dd3 > 0.0f)) << 16));
    }

    const int i0 = 4 * lane;                    // column offset within tile
    if (m0) atomicAdd(&scol[i0 + 0], acc0);
    if (m1) atomicAdd(&scol[i0 + 1], acc1);
    if (m2) atomicAdd(&scol[i0 + 2], acc2);
    if (m3) atomicAdd(&scol[i0 + 3], acc3);
    __syncthreads();

    const int ncols = cmax - s;                 // 124 (or 126 for last tile)
    if (threadIdx.x < ncols) {
        g_part[blockIdx.y * NPOS + (s + 1 + threadIdx.x)] = scol[threadIdx.x];
    }
}

// ---------------------------------------------------------------------------
// K2 (single block): sum strips -> gaussian conv -> min/max -> normalize.
// Gaussian tail beyond R = 9*w+1 is < exp(-81) ~ 6e-36: zero for fp32.
// ---------------------------------------------------------------------------
__global__ __launch_bounds__(1024) void k_vecnorm(const float* __restrict__ lpw,
                                                  const float* __restrict__ lvw) {
    __shared__ unsigned int scnt[NPOS];
    __shared__ float sgp[GTAB];
    __shared__ float sgv[GTAB];
    __shared__ float smn[32], smx[32];

    const int t = threadIdx.x;

    // Stage total packed counts (sum over 32 strips; L2-resident).
    for (int c = t; c < NPOS; c += 1024) {
        unsigned sum = 0;
        if (c >= 1 && c <= NPOS - 2) {
            #pragma unroll
            for (int k = 0; k < NSTRIP; k++) sum += g_part[k * NPOS + c];
        }
        scnt[c] = sum;
    }

    const float wp = expf(*lpw);
    const float wv = expf(*lvw);
    int R = (int)(9.0f * fmaxf(wp, wv)) + 1;
    if (R > GTAB - 1) R = GTAB - 1;

    for (int d = t; d <= R; d += 1024) {
        float fd = (float)d;
        float tp = fd / wp;
        float tv = fd / wv;
        sgp[d] = expf(-tp * tp);
        sgv[d] = expf(-tv * tv);
    }
    __syncthreads();

    float vals[4];
    float mn = FLT_MAX, mx = -FLT_MAX;
    #pragma unroll
    for (int q = 0; q < 4; q++) {
        const int p = t + q * 1024;
        float acc = 0.0f;
        for (int d = -R; d <= R; d++) {
            int c = p + d;
            if ((unsigned)(c - 1) <= (unsigned)(NPOS - 3)) {
                unsigned pk = scnt[c];
                int ad = d < 0 ? -d : d;
                acc += (float)(pk & 0xFFFFu) * sgp[ad]
                     + (float)(pk >> 16)     * sgv[ad];
            }
        }
        vals[q] = acc;
        mn = fminf(mn, acc);
        mx = fmaxf(mx, acc);
    }

    // Block min/max reduction.
    #pragma unroll
    for (int o = 16; o > 0; o >>= 1) {
        mn = fminf(mn, __shfl_xor_sync(0xFFFFFFFFu, mn, o));
        mx = fmaxf(mx, __shfl_xor_sync(0xFFFFFFFFu, mx, o));
    }
    if ((t & 31) == 0) { smn[t >> 5] = mn; smx[t >> 5] = mx; }
    __syncthreads();
    if (t < 32) {
        mn = smn[t]; mx = smx[t];
        #pragma unroll
        for (int o = 16; o > 0; o >>= 1) {
            mn = fminf(mn, __shfl_xor_sync(0xFFFFFFFFu, mn, o));
            mx = fmaxf(mx, __shfl_xor_sync(0xFFFFFFFFu, mx, o));
        }
        if (t == 0) { smn[0] = mn; smx[0] = mx; }
    }
    __syncthreads();
    mn = smn[0];
    const float denom = smx[0] - mn + 1e-6f;

    #pragma unroll
    for (int q = 0; q < 4; q++) {
        g_norm[t + q * 1024] = (vals[q] - mn) / denom;
    }
}

// ---------------------------------------------------------------------------
// K3: broadcast normalized vector to all 8192 rows (streaming stores).
// ---------------------------------------------------------------------------
__global__ __launch_bounds__(1024) void k_bcast(float* __restrict__ out) {
    const int t = threadIdx.x;
    const float4 v = ((const float4*)g_norm)[t];
    float4* o = (float4*)out + (size_t)blockIdx.x * 16 * 1024 + t;
    #pragma unroll
    for (int r = 0; r < 16; r++) {
        __stcs(o + (size_t)r * 1024, v);
    }
}

// ---------------------------------------------------------------------------
extern "C" void kernel_launch(void* const* d_in, const int* in_sizes, int n_in,
                              void* d_out, int out_size) {
    const float* x   = (const float*)d_in[0];
    const float* lpw = (const float*)d_in[1];
    const float* lvw = (const float*)d_in[2];
    float* out = (float*)d_out;

    k_counts<<<dim3(NTILES, NSTRIP), 256>>>(x);
    k_vecnorm<<<1, 1024>>>(lpw, lvw);
    k_bcast<<<NROWS / 16, 1024>>>(out);
}

// round 3
// speedup vs baseline: 1.2867x; 1.2867x over previous
#include <cuda_runtime.h>
#include <cstdint>
#include <cfloat>

// Shapes fixed by the problem: x is (64, 128, 4096) fp32.
#define NPOS   4096
#define NROWS  8192          // 64*128
#define NTILES 33            // tiles of 124 centers (last: 126)
#define NSTRIP 32            // 8192 rows / 256 rows-per-strip
#define RMAX   512           // gaussian radius cap (R=28 for width 3)

// Scratch in __device__ globals (no allocations allowed).
__device__ unsigned int g_part[NSTRIP * NPOS]; // per-strip packed counts
__device__ float        g_vec[NPOS];
__device__ int          g_min_bits;            // nonneg floats: int cmp == float cmp
__device__ int          g_max_bits;

// ---------------------------------------------------------------------------
// K1: count peaks/valleys per column position, per row-strip.
// Warp owns a 128-float column tile (float4/lane); 32 rows in 8 batches of 4
// explicitly front-loaded float4s (MLP=4/thread). Packed block-reduce via
// shared atomics, one non-atomic global store per column.
// dd matches the reference exactly: (x[p+1]-x[p]) - (x[p]-x[p-1]).
// ---------------------------------------------------------------------------
__global__ __launch_bounds__(256) void k_counts(const float* __restrict__ x) {
    __shared__ unsigned int scol[128];

    const int lane = threadIdx.x & 31;
    const int warp = threadIdx.x >> 5;          // 0..7
    const int tile = blockIdx.x;                // 0..32
    const int s    = tile * 124;                // tile covers x columns [s, s+128)
    const int cmax = (tile == NTILES - 1) ? (NPOS - 2) : (s + 124);
    const int p0   = s + 4 * lane + 1;

    // Reset min/max scalars for this graph replay (runs before k_vec).
    if (tile == 0 && blockIdx.y == 0 && threadIdx.x == 0) {
        g_min_bits = 0x7F800000;   // +inf
        g_max_bits = 0;            // values are >= 0
    }

    for (int i = threadIdx.x; i < 128; i += 256) scol[i] = 0u;
    __syncthreads();

    unsigned p0c = 0, p1c = 0, p2c = 0, p3c = 0;   // peak counts
    unsigned v0c = 0, v1c = 0, v2c = 0, v3c = 0;   // valley counts

    const int rowbase = blockIdx.y * 256 + warp * 32;
    const float* xb = x + (size_t)rowbase * NPOS + s;

    #pragma unroll 2
    for (int kb = 0; kb < 8; kb++) {
        float4 v[4];
        #pragma unroll
        for (int r = 0; r < 4; r++) {
            v[r] = __ldg((const float4*)(xb + (size_t)(kb * 4 + r) * NPOS) + lane);
        }
        #pragma unroll
        for (int r = 0; r < 4; r++) {
            // Seam values from the next lane (garbage in lane 31; its
            // dependent centers are masked out at the flush).
            float xn0 = __shfl_down_sync(0xFFFFFFFFu, v[r].x, 1);
            float xn1 = __shfl_down_sync(0xFFFFFFFFu, v[r].y, 1);

            float d0 = v[r].y - v[r].x;
            float d1 = v[r].z - v[r].y;
            float d2 = v[r].w - v[r].z;
            float d3 = xn0 - v[r].w;
            float d4 = xn1 - xn0;

            float dd0 = d1 - d0;   // center p0
            float dd1 = d2 - d1;   // center p0+1
            float dd2 = d3 - d2;   // center p0+2
            float dd3 = d4 - d3;   // center p0+3

            p0c += (dd0 < 0.0f); v0c += (dd0 > 0.0f);
            p1c += (dd1 < 0.0f); v1c += (dd1 > 0.0f);
            p2c += (dd2 < 0.0f); v2c += (dd2 > 0.0f);
            p3c += (dd3 < 0.0f); v3c += (dd3 > 0.0f);
        }
    }

    const int i0 = 4 * lane;
    if (p0 + 0 <= cmax) atomicAdd(&scol[i0 + 0], p0c | (v0c << 16));
    if (p0 + 1 <= cmax) atomicAdd(&scol[i0 + 1], p1c | (v1c << 16));
    if (p0 + 2 <= cmax) atomicAdd(&scol[i0 + 2], p2c | (v2c << 16));
    if (p0 + 3 <= cmax) atomicAdd(&scol[i0 + 3], p3c | (v3c << 16));
    __syncthreads();

    const int ncols = cmax - s;                 // 124 (126 for last tile)
    if (threadIdx.x < ncols) {
        g_part[blockIdx.y * NPOS + (s + 1 + threadIdx.x)] = scol[threadIdx.x];
    }
}

// ---------------------------------------------------------------------------
// K2: 32 blocks x 128 threads. Each block: strip-sum its halo'd column range
// into smem (zero-padded OOB), symmetric gaussian conv, write g_vec, and
// block-reduced atomic min/max. Gaussian tail beyond R = 9w+1 is < exp(-81).
// ---------------------------------------------------------------------------
__global__ __launch_bounds__(128) void k_vec(const float* __restrict__ lpw,
                                             const float* __restrict__ lvw) {
    __shared__ unsigned int scnt[128 + 2 * RMAX];
    __shared__ float sgp[RMAX + 1];
    __shared__ float sgv[RMAX + 1];
    __shared__ float smn[4], smx[4];

    const int t = threadIdx.x;

    const float wp = expf(*lpw);
    const float wv = expf(*lvw);
    int R = (int)(9.0f * fmaxf(wp, wv)) + 1;
    if (R > RMAX) R = RMAX;

    for (int d = t; d <= R; d += 128) {
        float fd = (float)d;
        float tp = fd / wp;
        float tv = fd / wv;
        sgp[d] = expf(-tp * tp);
        sgv[d] = expf(-tv * tv);
    }

    // Stage summed counts for columns [sbase, sbase+span) with zero padding.
    const int pbase = blockIdx.x * 128;      // outputs [pbase, pbase+128)
    const int sbase = pbase - R;
    const int span  = 128 + 2 * R;
    for (int j = t; j < span; j += 128) {
        const int c = sbase + j;
        unsigned sum = 0;
        if (c >= 1 && c <= NPOS - 2) {
            #pragma unroll 8
            for (int k = 0; k < NSTRIP; k++) sum += g_part[k * NPOS + c];
        }
        scnt[j] = sum;
    }
    __syncthreads();

    // Symmetric-pair convolution: packed u16 fields hold sums <= 16384, safe.
    const int ci = t + R;                    // smem index of this thread's center
    unsigned pk0 = scnt[ci];
    float acc = (float)(pk0 & 0xFFFFu) * sgp[0] + (float)(pk0 >> 16) * sgv[0];
    for (int d = 1; d <= R; d++) {
        unsigned pk = scnt[ci + d] + scnt[ci - d];
        acc += (float)(pk & 0xFFFFu) * sgp[d] + (float)(pk >> 16) * sgv[d];
    }
    g_vec[pbase + t] = acc;

    // Block min/max -> one atomic pair per block.
    float mn = acc, mx = acc;
    #pragma unroll
    for (int o = 16; o > 0; o >>= 1) {
        mn = fminf(mn, __shfl_xor_sync(0xFFFFFFFFu, mn, o));
        mx = fmaxf(mx, __shfl_xor_sync(0xFFFFFFFFu, mx, o));
    }
    if ((t & 31) == 0) { smn[t >> 5] = mn; smx[t >> 5] = mx; }
    __syncthreads();
    if (t == 0) {
        mn = fminf(fminf(smn[0], smn[1]), fminf(smn[2], smn[3]));
        mx = fmaxf(fmaxf(smx[0], smx[1]), fmaxf(smx[2], smx[3]));
        atomicMin(&g_min_bits, __float_as_int(mn));  // nonneg floats
        atomicMax(&g_max_bits, __float_as_int(mx));
    }
}

// ---------------------------------------------------------------------------
// K3: normalize on the fly + broadcast to all 8192 rows.
// ---------------------------------------------------------------------------
__global__ __launch_bounds__(1024) void k_bcast(float* __restrict__ out) {
    const int t = threadIdx.x;
    const float mn = __int_as_float(g_min_bits);
    const float inv = 1.0f / (__int_as_float(g_max_bits) - mn + 1e-6f);

    float4 v = ((const float4*)g_vec)[t];
    v.x = (v.x - mn) * inv;
    v.y = (v.y - mn) * inv;
    v.z = (v.z - mn) * inv;
    v.w = (v.w - mn) * inv;

    float4* o = (float4*)out + (size_t)blockIdx.x * 16 * 1024 + t;
    #pragma unroll
    for (int r = 0; r < 16; r++) {
        o[(size_t)r * 1024] = v;
    }
}

// ---------------------------------------------------------------------------
extern "C" void kernel_launch(void* const* d_in, const int* in_sizes, int n_in,
                              void* d_out, int out_size) {
    const float* x   = (const float*)d_in[0];
    const float* lpw = (const float*)d_in[1];
    const float* lvw = (const float*)d_in[2];
    float* out = (float*)d_out;

    k_counts<<<dim3(NTILES, NSTRIP), 256>>>(x);
    k_vec<<<NPOS / 128, 128>>>(lpw, lvw);
    k_bcast<<<NROWS / 16, 1024>>>(out);
}

// round 4
// speedup vs baseline: 1.3774x; 1.0705x over previous
#include <cuda_runtime.h>
#include <cstdint>
#include <cfloat>

// Shapes fixed by the problem: x is (64, 128, 4096) fp32.
#define NPOS   4096
#define NROWS  8192          // 64*128
#define NTILES 33            // tiles of 124 centers (last: 126)
#define NSTRIP 64            // 8192 rows / 128 rows-per-strip
#define RMAX   512           // gaussian radius cap (R=28 for width 3)

// Scratch in __device__ globals (no allocations allowed).
__device__ unsigned int g_part[NSTRIP * NPOS]; // per-strip packed counts
__device__ float        g_vec[NPOS];
__device__ int          g_min_bits;            // nonneg floats: int cmp == float cmp
__device__ int          g_max_bits;

// ---------------------------------------------------------------------------
// K1: count peaks/valleys per column position, per row-strip.
// Warp owns a 128-float column tile (float4 per lane), iterates 16 rows with
// one load per iteration (low register pressure; loads across unrolled iters
// are independent). Separate peak/valley register accumulators — no masking
// or packing in the inner loop; masks applied once at the flush.
// dd matches the reference exactly: (x[p+1]-x[p]) - (x[p]-x[p-1]).
// ---------------------------------------------------------------------------
__global__ __launch_bounds__(256) void k_counts(const float* __restrict__ x) {
    __shared__ unsigned int scol[128];

    const int lane = threadIdx.x & 31;
    const int warp = threadIdx.x >> 5;          // 0..7
    const int tile = blockIdx.x;                // 0..32
    const int s    = tile * 124;                // tile covers x columns [s, s+128)
    const int cmax = (tile == NTILES - 1) ? (NPOS - 2) : (s + 124);
    const int p0   = s + 4 * lane + 1;

    // Reset min/max scalars for this graph replay (runs before k_vec).
    if (tile == 0 && blockIdx.y == 0 && threadIdx.x == 0) {
        g_min_bits = 0x7F800000;   // +inf
        g_max_bits = 0;            // values are >= 0
    }

    for (int i = threadIdx.x; i < 128; i += 256) scol[i] = 0u;
    __syncthreads();

    unsigned p0c = 0, p1c = 0, p2c = 0, p3c = 0;   // peak counts
    unsigned v0c = 0, v1c = 0, v2c = 0, v3c = 0;   // valley counts

    const int rowbase = blockIdx.y * 128 + warp * 16;
    const float* xb = x + (size_t)rowbase * NPOS + s;

    #pragma unroll 4
    for (int k = 0; k < 16; k++) {
        float4 v = __ldcs((const float4*)(xb + (size_t)k * NPOS) + lane);
        // Seam values from the next lane (garbage in lane 31; its dependent
        // centers are masked out at the flush).
        float xn0 = __shfl_down_sync(0xFFFFFFFFu, v.x, 1);
        float xn1 = __shfl_down_sync(0xFFFFFFFFu, v.y, 1);

        float d0 = v.y - v.x;
        float d1 = v.z - v.y;
        float d2 = v.w - v.z;
        float d3 = xn0 - v.w;
        float d4 = xn1 - xn0;

        float dd0 = d1 - d0;   // center p0
        float dd1 = d2 - d1;   // center p0+1
        float dd2 = d3 - d2;   // center p0+2
        float dd3 = d4 - d3;   // center p0+3

        p0c += (dd0 < 0.0f); v0c += (dd0 > 0.0f);
        p1c += (dd1 < 0.0f); v1c += (dd1 > 0.0f);
        p2c += (dd2 < 0.0f); v2c += (dd2 > 0.0f);
        p3c += (dd3 < 0.0f); v3c += (dd3 > 0.0f);
    }

    const int i0 = 4 * lane;
    if (p0 + 0 <= cmax) atomicAdd(&scol[i0 + 0], p0c | (v0c << 16));
    if (p0 + 1 <= cmax) atomicAdd(&scol[i0 + 1], p1c | (v1c << 16));
    if (p0 + 2 <= cmax) atomicAdd(&scol[i0 + 2], p2c | (v2c << 16));
    if (p0 + 3 <= cmax) atomicAdd(&scol[i0 + 3], p3c | (v3c << 16));
    __syncthreads();

    const int ncols = cmax - s;                 // 124 (126 for last tile)
    if (threadIdx.x < ncols) {
        g_part[blockIdx.y * NPOS + (s + 1 + threadIdx.x)] = scol[threadIdx.x];
    }
}

// ---------------------------------------------------------------------------
// K2: 32 blocks x 128 threads. Each block: strip-sum its halo'd column range
// into smem (zero-padded OOB), symmetric gaussian conv, write g_vec, and
// block-reduced atomic min/max. Gaussian tail beyond R = 9w+1 is < exp(-81).
// ---------------------------------------------------------------------------
__global__ __launch_bounds__(128) void k_vec(const float* __restrict__ lpw,
                                             const float* __restrict__ lvw) {
    __shared__ unsigned int scnt[128 + 2 * RMAX];
    __shared__ float sgp[RMAX + 1];
    __shared__ float sgv[RMAX + 1];
    __shared__ float smn[4], smx[4];

    const int t = threadIdx.x;

    const float wp = expf(*lpw);
    const float wv = expf(*lvw);
    int R = (int)(9.0f * fmaxf(wp, wv)) + 1;
    if (R > RMAX) R = RMAX;

    for (int d = t; d <= R; d += 128) {
        float fd = (float)d;
        float tp = fd / wp;
        float tv = fd / wv;
        sgp[d] = expf(-tp * tp);
        sgv[d] = expf(-tv * tv);
    }

    // Stage summed counts for columns [sbase, sbase+span) with zero padding.
    const int pbase = blockIdx.x * 128;      // outputs [pbase, pbase+128)
    const int sbase = pbase - R;
    const int span  = 128 + 2 * R;
    for (int j = t; j < span; j += 128) {
        const int c = sbase + j;
        unsigned sum = 0;
        if (c >= 1 && c <= NPOS - 2) {
            #pragma unroll 8
            for (int k = 0; k < NSTRIP; k++) sum += g_part[k * NPOS + c];
        }
        scnt[j] = sum;
    }
    __syncthreads();

    // Symmetric-pair convolution: packed u16 fields hold sums <= 16384, safe.
    const int ci = t + R;                    // smem index of this thread's center
    unsigned pk0 = scnt[ci];
    float acc = (float)(pk0 & 0xFFFFu) * sgp[0] + (float)(pk0 >> 16) * sgv[0];
    for (int d = 1; d <= R; d++) {
        unsigned pk = scnt[ci + d] + scnt[ci - d];
        acc += (float)(pk & 0xFFFFu) * sgp[d] + (float)(pk >> 16) * sgv[d];
    }
    g_vec[pbase + t] = acc;

    // Block min/max -> one atomic pair per block.
    float mn = acc, mx = acc;
    #pragma unroll
    for (int o = 16; o > 0; o >>= 1) {
        mn = fminf(mn, __shfl_xor_sync(0xFFFFFFFFu, mn, o));
        mx = fmaxf(mx, __shfl_xor_sync(0xFFFFFFFFu, mx, o));
    }
    if ((t & 31) == 0) { smn[t >> 5] = mn; smx[t >> 5] = mx; }
    __syncthreads();
    if (t == 0) {
        mn = fminf(fminf(smn[0], smn[1]), fminf(smn[2], smn[3]));
        mx = fmaxf(fmaxf(smx[0], smx[1]), fmaxf(smx[2], smx[3]));
        atomicMin(&g_min_bits, __float_as_int(mn));  // nonneg floats
        atomicMax(&g_max_bits, __float_as_int(mx));
    }
}

// ---------------------------------------------------------------------------
// K3: normalize on the fly + broadcast to all 8192 rows.
// ---------------------------------------------------------------------------
__global__ __launch_bounds__(1024) void k_bcast(float* __restrict__ out) {
    const int t = threadIdx.x;
    const float mn = __int_as_float(g_min_bits);
    const float inv = 1.0f / (__int_as_float(g_max_bits) - mn + 1e-6f);

    float4 v = ((const float4*)g_vec)[t];
    v.x = (v.x - mn) * inv;
    v.y = (v.y - mn) * inv;
    v.z = (v.z - mn) * inv;
    v.w = (v.w - mn) * inv;

    float4* o = (float4*)out + (size_t)blockIdx.x * 16 * 1024 + t;
    #pragma unroll
    for (int r = 0; r < 16; r++) {
        o[(size_t)r * 1024] = v;
    }
}

// ---------------------------------------------------------------------------
extern "C" void kernel_launch(void* const* d_in, const int* in_sizes, int n_in,
                              void* d_out, int out_size) {
    const float* x   = (const float*)d_in[0];
    const float* lpw = (const float*)d_in[1];
    const float* lvw = (const float*)d_in[2];
    float* out = (float*)d_out;

    k_counts<<<dim3(NTILES, NSTRIP), 256>>>(x);
    k_vec<<<NPOS / 128, 128>>>(lpw, lvw);
    k_bcast<<<NROWS / 16, 1024>>>(out);
}